// round 17
// baseline (speedup 1.0000x reference)
#include <cuda_runtime.h>
#include <cuda_fp16.h>
#include <cstdint>

#define NV   32768
#define KC   8192
#define DIMV 64
#define ND   (NV * DIMV)

#define CCHUNK  128                 // codes per chunk
#define NCHUNKS (KC / CCHUNK)       // 64
#define MTILE   64                  // z rows per block
#define NBLK    (NV / MTILE)        // 512
#define ASTRIDE 144                 // bytes per fp16 row (128B + 16B pad)

// main smem layout (bytes)
#define SM_AH   0                   // 64 * 144 = 9216
#define SM_B    9216                // 2 bufs * 18432
#define SM_BB(i) (SM_B + (i) * 18432)
#define SM_ESQ  46080               // 2 * 512
#define SM_RB   47104               // 2*64 floats
#define SM_RB2  47616
#define SM_RI   48128
#define SM_WL   48640               // 8 floats
#define SMEM_MAIN 48672

// fixup geometry (proven R14-R16)
#define FROWS   16
#define FCCH    256
#define FNCH    (KC / FCCH)
#define FSTR    272
#define FEBUF   (FCCH * FSTR)
#define FSM_Z   0
#define FSM_E   4352
#define FSM_RED 143616
#define SMEM_FIX 144640

__device__ __align__(256) __half g_cbh[KC * DIMV];
__device__ float g_esq[KC];         // 0.5*||e||^2 exact fp32
__device__ float g_block_sums[NBLK];
__device__ unsigned g_maxne_bits;   // max_k ||e_k|| as float bits
__device__ int   g_fix_count;
__device__ int   g_fix_list[NV];
__device__ float g_loss_corr;

__device__ __forceinline__ void cp16(void* dst_s, const void* src_g) {
    uint32_t d = (uint32_t)__cvta_generic_to_shared(dst_s);
    asm volatile("cp.async.cg.shared.global [%0], [%1], 16;" :: "r"(d), "l"(src_g));
}
#define CP_COMMIT() asm volatile("cp.async.commit_group;" ::: "memory")
#define CP_WAIT1()  asm volatile("cp.async.wait_group 1;" ::: "memory")
#define CP_WAIT0()  asm volatile("cp.async.wait_group 0;" ::: "memory")

__device__ __forceinline__ void mma16816(float* c, const uint32_t* a,
                                         uint32_t b0, uint32_t b1) {
    asm volatile(
        "mma.sync.aligned.m16n8k16.row.col.f32.f16.f16.f32 "
        "{%0,%1,%2,%3}, {%4,%5,%6,%7}, {%8,%9}, {%0,%1,%2,%3};"
        : "+f"(c[0]), "+f"(c[1]), "+f"(c[2]), "+f"(c[3])
        : "r"(a[0]), "r"(a[1]), "r"(a[2]), "r"(a[3]), "r"(b0), "r"(b1));
}

__device__ __forceinline__ void ffma2(unsigned long long &d,
                                      unsigned long long a,
                                      unsigned long long b) {
    asm("fma.rn.f32x2 %0, %1, %2, %0;" : "+l"(d) : "l"(a), "l"(b));
}

// ---------------- K1: codebook fp16 + half-norms + maxnorm + resets ----------------
__global__ void vq_prep(const float* __restrict__ cb) {
    int k = blockIdx.x * blockDim.x + threadIdx.x;
    if (k == 0) { g_fix_count = 0; g_loss_corr = 0.f; }
    if (k < KC) {
        float s = 0.f;
        #pragma unroll
        for (int d = 0; d < DIMV; d++) {
            float v = cb[(size_t)k * DIMV + d];
            s += v * v;
            g_cbh[(size_t)k * DIMV + d] = __float2half_rn(v);
        }
        g_esq[k] = 0.5f * s;
        float nrm = sqrtf(s);
        #pragma unroll
        for (int off = 16; off >= 1; off >>= 1)
            nrm = fmaxf(nrm, __shfl_xor_sync(0xffffffffu, nrm, off));
        if ((threadIdx.x & 31) == 0)
            atomicMax(&g_maxne_bits, __float_as_uint(nrm));  // idempotent across replays
    }
}

// ---------------- K2: fp16 HMMA GEMM + argmin/margin + gather ----------------
__device__ __forceinline__ void cp_chunk(char* smem, int chunk, int buf, int tid) {
    const __half* sh = g_cbh + (size_t)chunk * CCHUNK * DIMV;
    char* dh = smem + SM_BB(buf);
    #pragma unroll
    for (int n = 0; n < 4; n++) {
        int q = tid + 256 * n;          // 0..1023 16B-quads
        int code = q >> 3, dd = q & 7;
        cp16(dh + code * ASTRIDE + dd * 16, sh + code * DIMV + dd * 8);
    }
    if (tid < 32)
        cp16(smem + SM_ESQ + (buf ? 512 : 0) + tid * 16, g_esq + chunk * CCHUNK + tid * 4);
}

__global__ __launch_bounds__(256, 3) void vq_main(
    const float* __restrict__ z, const float* __restrict__ cb,
    float* __restrict__ out, int out_size)
{
    extern __shared__ char smem[];
    const int tid = threadIdx.x, lane = tid & 31, wid = tid >> 5;
    const int g = lane >> 2, t = lane & 3;
    const int mwarp = wid >> 1, nwarp = wid & 1;
    const int row0 = blockIdx.x * MTILE;

    // A tile: z fp32 -> fp16
    #pragma unroll
    for (int n = 0; n < 8; n++) {
        int i = tid + 256 * n;          // 0..2047 float2 slots
        int r = i >> 5, d2 = i & 31;
        float2 v = reinterpret_cast<const float2*>(z + (size_t)(row0 + r) * DIMV)[d2];
        *reinterpret_cast<__half2*>(smem + SM_AH + r * ASTRIDE + d2 * 4) =
            __halves2half2(__float2half_rn(v.x), __float2half_rn(v.y));
    }

    cp_chunk(smem, 0, 0, tid);
    CP_COMMIT();

    float best[2], best2[2];
    int   bidx[2];
    #pragma unroll
    for (int s = 0; s < 2; s++) { best[s] = 3.4e38f; best2[s] = 3.4e38f; bidx[s] = 0; }

    const char* Ah = smem + SM_AH;
    const int abase = (mwarp * 16 + g) * ASTRIDE + t * 4;
    const int bbase = (nwarp * 64 + g) * ASTRIDE + t * 4;

    for (int c = 0; c < NCHUNKS; c++) {
        const int b = c & 1;
        CP_WAIT0();
        __syncthreads();                // chunk c visible; all warps done with buf b' (c-1)
        if (c + 1 < NCHUNKS) { cp_chunk(smem, c + 1, (c + 1) & 1, tid); CP_COMMIT(); }

        const char* Bh = smem + SM_BB(b);
        const float* esq_s = reinterpret_cast<const float*>(smem + SM_ESQ + (b ? 512 : 0));

        float acc[8][4];
        #pragma unroll
        for (int nt = 0; nt < 8; nt++)
            #pragma unroll
            for (int q = 0; q < 4; q++) acc[nt][q] = 0.f;

        #pragma unroll
        for (int ks = 0; ks < 4; ks++) {
            uint32_t ahf[4];
            int ao = abase + ks * 32;
            ahf[0] = *reinterpret_cast<const uint32_t*>(Ah + ao);
            ahf[1] = *reinterpret_cast<const uint32_t*>(Ah + ao + 8 * ASTRIDE);
            ahf[2] = *reinterpret_cast<const uint32_t*>(Ah + ao + 16);
            ahf[3] = *reinterpret_cast<const uint32_t*>(Ah + ao + 8 * ASTRIDE + 16);
            #pragma unroll
            for (int nt = 0; nt < 8; nt++) {
                int bo = bbase + nt * 8 * ASTRIDE + ks * 32;
                uint32_t bh0 = *reinterpret_cast<const uint32_t*>(Bh + bo);
                uint32_t bh1 = *reinterpret_cast<const uint32_t*>(Bh + bo + 16);
                mma16816(acc[nt], ahf, bh0, bh1);
            }
        }

        #pragma unroll
        for (int nt = 0; nt < 8; nt++) {
            int nloc = nwarp * 64 + nt * 8 + 2 * t;
            float es0 = esq_s[nloc], es1 = esq_s[nloc + 1];
            int n0 = c * CCHUNK + nloc;
            float v00 = es0 - acc[nt][0];   // row g,   col n0
            float v01 = es1 - acc[nt][1];   // row g,   col n0+1
            float v10 = es0 - acc[nt][2];   // row g+8, col n0
            float v11 = es1 - acc[nt][3];   // row g+8, col n0+1
            if (v00 < best[0]) { best2[0] = best[0]; best[0] = v00; bidx[0] = n0; }
            else if (v00 < best2[0]) best2[0] = v00;
            if (v01 < best[0]) { best2[0] = best[0]; best[0] = v01; bidx[0] = n0 + 1; }
            else if (v01 < best2[0]) best2[0] = v01;
            if (v10 < best[1]) { best2[1] = best[1]; best[1] = v10; bidx[1] = n0; }
            else if (v10 < best2[1]) best2[1] = v10;
            if (v11 < best[1]) { best2[1] = best[1]; best[1] = v11; bidx[1] = n0 + 1; }
            else if (v11 < best2[1]) best2[1] = v11;
        }
        // no bottom sync: next iter's top sync precedes the next cp issue
    }

    // reduce over t (lanes xor 1,2 share rows)
    #pragma unroll
    for (int s = 0; s < 2; s++) {
        float b1 = best[s], b2 = best2[s];
        int   i1 = bidx[s];
        #pragma unroll
        for (int off = 1; off <= 2; off <<= 1) {
            float ob  = __shfl_xor_sync(0xffffffffu, b1, off);
            float ob2 = __shfl_xor_sync(0xffffffffu, b2, off);
            int   oi  = __shfl_xor_sync(0xffffffffu, i1, off);
            if (ob < b1 || (ob == b1 && oi < i1)) { b2 = fminf(b1, ob2); b1 = ob; i1 = oi; }
            else                                  { b2 = fminf(ob, b2); }
        }
        best[s] = b1; best2[s] = b2; bidx[s] = i1;
    }
    if (t == 0) {
        float* rb  = reinterpret_cast<float*>(smem + SM_RB);
        float* rb2 = reinterpret_cast<float*>(smem + SM_RB2);
        int*   ri  = reinterpret_cast<int*>(smem + SM_RI);
        #pragma unroll
        for (int s = 0; s < 2; s++) {
            int row = mwarp * 16 + g + s * 8;
            rb [nwarp * 64 + row] = best[s];
            rb2[nwarp * 64 + row] = best2[s];
            ri [nwarp * 64 + row] = bidx[s];
        }
    }
    __syncthreads();

    float lsum = 0.f;
    if (tid < MTILE) {
        const float* rb  = reinterpret_cast<const float*>(smem + SM_RB);
        const float* rb2 = reinterpret_cast<const float*>(smem + SM_RB2);
        const int*   ri  = reinterpret_cast<const int*>(smem + SM_RI);
        float b0 = rb[tid],      b20 = rb2[tid];      int i0 = ri[tid];
        float b1 = rb[64 + tid], b21 = rb2[64 + tid]; int i1 = ri[64 + tid];
        float bb, bb2; int bi;
        if (b1 < b0 || (b1 == b0 && i1 < i0)) { bb = b1; bi = i1; bb2 = fminf(b0, b21); }
        else                                  { bb = b0; bi = i0; bb2 = fminf(b1, b20); }

        const int grow = row0 + tid;
        const float4* crow = reinterpret_cast<const float4*>(cb + (size_t)bi * DIMV);
        const float4* zrow = reinterpret_cast<const float4*>(z + (size_t)grow * DIMV);
        float4* qrow = reinterpret_cast<float4*>(out + (size_t)grow * DIMV);
        float zsq = 0.f;
        #pragma unroll
        for (int j = 0; j < 16; j++) {
            float4 e = crow[j], zz = zrow[j];
            qrow[j] = e;                    // straight-through: quantized == codebook[idx]
            float dx = zz.x - e.x, dy = zz.y - e.y;
            float dz = zz.z - e.z, dw = zz.w - e.w;
            lsum += dx * dx + dy * dy + dz * dz + dw * dw;
            zsq  += zz.x * zz.x + zz.y * zz.y + zz.z * zz.z + zz.w * zz.w;
        }
        // rigorous fp16-rounding bound: B = 2^-10 * ||z|| * max||e|| * 1.01 + 1e-3
        float B = sqrtf(zsq) * __uint_as_float(g_maxne_bits) * (1.01f / 1024.f) + 1e-3f;
        if (bb2 - bb < 2.f * B) {
            int pos = atomicAdd(&g_fix_count, 1);
            g_fix_list[pos] = grow;
        }
        if (out_size >= ND + 2 + NV) out[ND + 2 + grow] = (float)bi;
    }

    #pragma unroll
    for (int off = 16; off >= 1; off >>= 1)
        lsum += __shfl_xor_sync(0xffffffffu, lsum, off);
    float* wl = reinterpret_cast<float*>(smem + SM_WL);
    if (lane == 0) wl[wid] = lsum;
    __syncthreads();
    if (tid == 0) {
        float bsum = 0.f;
        #pragma unroll
        for (int w = 0; w < 8; w++) bsum += wl[w];
        g_block_sums[blockIdx.x] = bsum;
    }
}

// ---------------- K3: exact fp32 rescan of flagged rows (proven R14-R16) ----------------
__global__ __launch_bounds__(256, 1) void vq_fixup(
    const float* __restrict__ z, const float* __restrict__ cb,
    float* __restrict__ out, int out_size)
{
    extern __shared__ char fsm[];
    if (out_size < ND + 2 + NV) return;
    const int tid = threadIdx.x, lane = tid & 31, wid = tid >> 5;
    const int row_t = lane & 3, csub = lane >> 2;
    const int ct = wid * 8 + csub;
    int nfix = g_fix_count; if (nfix > NV) nfix = NV;

    float* z_s = reinterpret_cast<float*>(fsm + FSM_Z);
    float* rbf = reinterpret_cast<float*>(fsm + FSM_RED);
    int*   rif = reinterpret_cast<int*>(rbf + 128);

    for (int g = blockIdx.x; g * FROWS < nfix; g += gridDim.x) {
        const int base = g * FROWS;
        const int cnt  = min(FROWS, nfix - base);
        __syncthreads();

        for (int i = tid; i < FROWS * 16; i += 256) {
            int r = i >> 4, qd = i & 15;
            int zr = g_fix_list[base + min(r, cnt - 1)];
            float4 v = reinterpret_cast<const float4*>(z + (size_t)zr * DIMV)[qd];
            *reinterpret_cast<float4*>(z_s + r * 68 + qd * 4) = v;
        }
        #pragma unroll
        for (int n = 0; n < 16; n++) {
            int q = tid + 256 * n;
            int code = q >> 4, dd = q & 15;
            cp16(fsm + FSM_E + code * FSTR + dd * 16, cb + (size_t)code * DIMV + dd * 4);
        }
        CP_COMMIT();

        float best[4];
        int   bidx[4];
        #pragma unroll
        for (int k = 0; k < 4; k++) { best[k] = 3.4e38f; bidx[k] = 0; }

        for (int c = 0; c < FNCH; c++) {
            const int b = c & 1;
            if (c + 1 < FNCH) {
                const float* src = cb + (size_t)(c + 1) * FCCH * DIMV;
                char* d = fsm + FSM_E + ((c + 1) & 1) * FEBUF;
                #pragma unroll
                for (int n = 0; n < 16; n++) {
                    int q = tid + 256 * n;
                    int code = q >> 4, dd = q & 15;
                    cp16(d + code * FSTR + dd * 16, src + (size_t)code * DIMV + dd * 4);
                }
                CP_COMMIT(); CP_WAIT1();
            } else CP_WAIT0();
            __syncthreads();

            const char* Eb = fsm + FSM_E + b * FEBUF;
            unsigned long long acc[4][4];
            #pragma unroll
            for (int k = 0; k < 4; k++)
                #pragma unroll
                for (int j = 0; j < 4; j++) acc[k][j] = 0ull;

            #pragma unroll 8
            for (int d2 = 0; d2 < 32; d2++) {
                unsigned long long zf[4], ef[4];
                #pragma unroll
                for (int k = 0; k < 4; k++)
                    zf[k] = *reinterpret_cast<const unsigned long long*>(
                        z_s + (row_t + 4 * k) * 68 + d2 * 2);
                #pragma unroll
                for (int j = 0; j < 4; j++)
                    ef[j] = *reinterpret_cast<const unsigned long long*>(
                        Eb + (ct + 64 * j) * FSTR + d2 * 8);
                #pragma unroll
                for (int k = 0; k < 4; k++)
                    #pragma unroll
                    for (int j = 0; j < 4; j++) ffma2(acc[k][j], zf[k], ef[j]);
            }

            #pragma unroll
            for (int j = 0; j < 4; j++) {
                int code = c * FCCH + ct + 64 * j;
                float es = __ldg(&g_esq[code]);
                #pragma unroll
                for (int k = 0; k < 4; k++) {
                    float lo = __uint_as_float((unsigned)(acc[k][j] & 0xffffffffull));
                    float hi = __uint_as_float((unsigned)(acc[k][j] >> 32));
                    float s = es - (lo + hi);
                    if (s < best[k]) { best[k] = s; bidx[k] = code; }
                }
            }
            __syncthreads();
        }

        #pragma unroll
        for (int k = 0; k < 4; k++) {
            float b1 = best[k]; int i1 = bidx[k];
            #pragma unroll
            for (int off = 4; off <= 16; off <<= 1) {
                float ob = __shfl_xor_sync(0xffffffffu, b1, off);
                int   oi = __shfl_xor_sync(0xffffffffu, i1, off);
                if (ob < b1 || (ob == b1 && oi < i1)) { b1 = ob; i1 = oi; }
            }
            best[k] = b1; bidx[k] = i1;
        }
        if (csub == 0) {
            #pragma unroll
            for (int k = 0; k < 4; k++) {
                int r = row_t + 4 * k;
                rbf[wid * 16 + r] = best[k];
                rif[wid * 16 + r] = bidx[k];
            }
        }
        __syncthreads();

        if (tid < cnt) {
            float b1 = 3.4e38f; int i1 = 0;
            #pragma unroll
            for (int w = 0; w < 8; w++) {
                float ob = rbf[w * 16 + tid]; int oi = rif[w * 16 + tid];
                if (ob < b1 || (ob == b1 && oi < i1)) { b1 = ob; i1 = oi; }
            }
            const int row  = g_fix_list[base + tid];
            const int oldi = (int)out[ND + 2 + row];
            if (i1 != oldi) {
                float lold = 0.f, lnew = 0.f;
                #pragma unroll
                for (int d = 0; d < DIMV; d++) {
                    float zz = z[(size_t)row * DIMV + d];
                    float eo = cb[(size_t)oldi * DIMV + d];
                    float en = cb[(size_t)i1 * DIMV + d];
                    lold += (zz - eo) * (zz - eo);
                    lnew += (zz - en) * (zz - en);
                }
                atomicAdd(&g_loss_corr, lnew - lold);
                out[ND + 2 + row] = (float)i1;
                #pragma unroll
                for (int j = 0; j < 16; j++)
                    reinterpret_cast<float4*>(out + (size_t)row * DIMV)[j] =
                        reinterpret_cast<const float4*>(cb + (size_t)i1 * DIMV)[j];
            }
        }
    }
}

// ---------------- K4: deterministic final losses ----------------
__global__ void vq_finalize(float* __restrict__ out, int out_size) {
    __shared__ float ws[8];
    int tid = threadIdx.x;
    float s = g_block_sums[tid] + g_block_sums[tid + 256];   // NBLK == 512
    #pragma unroll
    for (int off = 16; off >= 1; off >>= 1)
        s += __shfl_xor_sync(0xffffffffu, s, off);
    if ((tid & 31) == 0) ws[tid >> 5] = s;
    __syncthreads();
    if (tid == 0) {
        float b = 0.f;
        #pragma unroll
        for (int w = 0; w < 8; w++) b += ws[w];
        float m = (b + g_loss_corr) / (float)ND;
        if (out_size >= ND + 2) {
            out[ND]     = m;   // vq_loss
            out[ND + 1] = m;   // commitment_loss
        }
    }
}

extern "C" void kernel_launch(void* const* d_in, const int* in_sizes, int n_in,
                              void* d_out, int out_size) {
    const float* a = (const float*)d_in[0];
    const float* b = (const float*)d_in[1];
    const float* z;
    const float* cb;
    if (in_sizes[0] == NV * DIMV) { z = a; cb = b; }
    else                          { z = b; cb = a; }
    float* out = (float*)d_out;

    cudaFuncSetAttribute(vq_main,  cudaFuncAttributeMaxDynamicSharedMemorySize, SMEM_MAIN);
    cudaFuncSetAttribute(vq_fixup, cudaFuncAttributeMaxDynamicSharedMemorySize, SMEM_FIX);

    vq_prep<<<KC / 128, 128>>>(cb);
    vq_main<<<NBLK, 256, SMEM_MAIN>>>(z, cb, out, out_size);
    vq_fixup<<<512, 256, SMEM_FIX>>>(z, cb, out, out_size);
    vq_finalize<<<1, 256>>>(out, out_size);
}